// round 12
// baseline (speedup 1.0000x reference)
#include <cuda_runtime.h>
#include <cuda_bf16.h>
#include <cuda_fp16.h>
#include <cstdint>
#include <cstddef>

#define BB 8
#define LL 2048
#define DD 1024

// ---------------- scratch (device globals; allocation-free) ----------------
__device__ float g_ks[BB * LL];
__device__ float g_e[BB * LL];
__device__ float g_zinv[BB * LL];
__device__ int g_is32;
__device__ uint32_t g_maskb[(size_t)BB * LL * (LL / 32)];  // bit s%32 of word: 1 = masked
__device__ __half g_ut[(size_t)BB * DD * LL];              // U^T fp16: [b][d][s]

// ---------------- helpers ----------------
static __device__ __forceinline__ uint32_t smem_u32(const void* p) {
    uint32_t a;
    asm("{ .reg .u64 t; cvta.to.shared.u64 t, %1; cvt.u32.u64 %0, t; }" : "=r"(a) : "l"(p));
    return a;
}

#define STS128V(a, r0, r1, r2, r3) \
    asm volatile("st.shared.v4.b32 [%0], {%1, %2, %3, %4};" :: "r"(a), "r"(r0), "r"(r1), "r"(r2), "r"(r3) : "memory")

#define CPASYNC16(dst, src) \
    asm volatile("cp.async.cg.shared.global [%0], [%1], 16;" :: "r"(dst), "l"(src) : "memory")
#define CPCOMMIT() asm volatile("cp.async.commit_group;" ::: "memory")
#define CPWAIT1() asm volatile("cp.async.wait_group 1;" ::: "memory")

static __device__ __forceinline__ void ldsm4(uint32_t* r, uint32_t addr) {
    asm volatile("ldmatrix.sync.aligned.m8n8.x4.shared.b16 {%0,%1,%2,%3}, [%4];"
                 : "=r"(r[0]), "=r"(r[1]), "=r"(r[2]), "=r"(r[3]) : "r"(addr));
}

static __device__ __forceinline__ void mma_f16(float* c, const uint32_t* a, const uint32_t* b) {
    asm volatile(
        "mma.sync.aligned.m16n8k16.row.col.f32.f16.f16.f32 "
        "{%0,%1,%2,%3}, {%4,%5,%6,%7}, {%8,%9}, {%0,%1,%2,%3};"
        : "+f"(c[0]), "+f"(c[1]), "+f"(c[2]), "+f"(c[3])
        : "r"(a[0]), "r"(a[1]), "r"(a[2]), "r"(a[3]), "r"(b[0]), "r"(b[1]));
}

// swizzled SMEM offset: rows are 128B (8 x 16B chunks)
#define SA(row, chunk) ((uint32_t)((row) * 128 + ((((uint32_t)(chunk)) ^ ((uint32_t)(row) & 7u)) << 4)))

// expand 16 mask bits -> 8 fp16x2 words (1.0 where bit==0)
static __device__ __forceinline__ void expand_bits16(uint32_t m, uint32_t* r) {
#pragma unroll
    for (int i = 0; i < 8; i++) {
        uint32_t lo = (m >> (2 * i)) & 1u;
        uint32_t hi = (m >> (2 * i + 1)) & 1u;
        r[i] = (lo ? 0u : 0x3C00u) | (hi ? 0u : 0x3C000000u);
    }
}
// expand 32 bits -> 16 words (fallback kernel)
static __device__ __forceinline__ void expand_bits(uint32_t m, uint32_t* r) {
#pragma unroll
    for (int i = 0; i < 16; i++) {
        uint32_t lo = (m >> (2 * i)) & 1u;
        uint32_t hi = (m >> (2 * i + 1)) & 1u;
        r[i] = (lo ? 0u : 0x3C00u) | (hi ? 0u : 0x3C000000u);
    }
}

// ---------------- Pass 0: detect mask dtype (int32 vs uint8) ----------------
__global__ void detect_kernel(const unsigned int* m) {
    __shared__ int s;
    if (threadIdx.x == 0) s = 0;
    __syncthreads();
    if (m[threadIdx.x] & 0xFFFFFF00u) atomicOr(&s, 1);
    __syncthreads();
    if (threadIdx.x == 0) g_is32 = s ? 0 : 1;
}

// ---------------- Pass 1: k_s[b,s] = k . W2 + b2 ----------------
__global__ __launch_bounds__(256) void ks_kernel(const float* __restrict__ k,
                                                 const float* __restrict__ W2,
                                                 const float* __restrict__ b2) {
    int w = threadIdx.x >> 5, lane = threadIdx.x & 31;
    int r = blockIdx.x * 8 + w;
    const float4* kr = (const float4*)(k + (size_t)r * DD);
    const float4* w4 = (const float4*)W2;
    float s = 0.f;
#pragma unroll
    for (int i = 0; i < 8; i++) {
        float4 a = kr[lane + 32 * i];
        float4 b = w4[lane + 32 * i];
        s += a.x * b.x + a.y * b.y + a.z * b.z + a.w * b.w;
    }
#pragma unroll
    for (int o = 16; o; o >>= 1) s += __shfl_xor_sync(0xFFFFFFFFu, s, o);
    if (lane == 0) g_ks[r] = s + b2[0];
}

// ---------------- Pass 2: per-b max and e = exp(ks - max) ----------------
__global__ __launch_bounds__(256) void maxexp_kernel() {
    int b = blockIdx.x;
    __shared__ float red[256];
    float m = -1e30f;
    for (int i = threadIdx.x; i < LL; i += 256) m = fmaxf(m, g_ks[b * LL + i]);
    red[threadIdx.x] = m;
    __syncthreads();
    for (int s = 128; s; s >>= 1) {
        if (threadIdx.x < s) red[threadIdx.x] = fmaxf(red[threadIdx.x], red[threadIdx.x + s]);
        __syncthreads();
    }
    float M = red[0];
    for (int i = threadIdx.x; i < LL; i += 256) g_e[b * LL + i] = expf(g_ks[b * LL + i] - M);
}

// ---------------- Pass 3: U^T fp16 build, 64x64 tiles, vectorized ----------------
__global__ __launch_bounds__(256) void ut_kernel(const float* __restrict__ v) {
    __shared__ float tile[64][65];
    int b = blockIdx.z;
    int s0 = blockIdx.y * 64, d0 = blockIdx.x * 64;
    int t = threadIdx.x;
    int sl = t >> 2, f4 = t & 3;
    float e = g_e[b * LL + s0 + sl];
    const float4* vr = (const float4*)(v + ((size_t)b * LL + s0 + sl) * DD + d0);
#pragma unroll
    for (int i = 0; i < 4; i++) {
        int c4 = f4 + 4 * i;
        float4 val = vr[c4];
        tile[sl][c4 * 4 + 0] = val.x * e;
        tile[sl][c4 * 4 + 1] = val.y * e;
        tile[sl][c4 * 4 + 2] = val.z * e;
        tile[sl][c4 * 4 + 3] = val.w * e;
    }
    __syncthreads();
    int dl = t >> 2, q = t & 3;
    __half* orow = g_ut + ((size_t)b * DD + d0 + dl) * LL + s0 + q * 16;
    uint32_t pk[8];
#pragma unroll
    for (int j = 0; j < 8; j++) {
        __half2 h2 = __floats2half2_rn(tile[q * 16 + 2 * j][dl], tile[q * 16 + 2 * j + 1][dl]);
        pk[j] = *(uint32_t*)&h2;
    }
    ((uint4*)orow)[0] = make_uint4(pk[0], pk[1], pk[2], pk[3]);
    ((uint4*)orow)[1] = make_uint4(pk[4], pk[5], pk[6], pk[7]);
}

// ---------------- Pass 4: fused bitpack + Z + attn ----------------
__global__ __launch_bounds__(256) void zattn_kernel(const void* __restrict__ maskp,
                                                    float* __restrict__ attn) {
    __shared__ __align__(16) float se[LL];
    int b = blockIdx.x >> 8;
    int l0 = (blockIdx.x & 255) * 8;
    for (int i = threadIdx.x; i < LL; i += 256) se[i] = g_e[b * LL + i];
    __syncthreads();
    int w = threadIdx.x >> 5, lane = threadIdx.x & 31;
    int l = l0 + w;
    const float4* e4 = (const float4*)se;
    uint32_t mw[16];
    if (g_is32) {
        const uint4* mrow = (const uint4*)((const int*)maskp + (size_t)(b * LL + l) * LL);
#pragma unroll
        for (int i = 0; i < 16; i++) {
            uint4 wv = mrow[lane + 32 * i];
            mw[i] = (wv.x ? 1u : 0u) | (wv.y ? 0x100u : 0u) |
                    (wv.z ? 0x10000u : 0u) | (wv.w ? 0x1000000u : 0u);
        }
    } else {
        const uint32_t* mrow = (const uint32_t*)((const unsigned char*)maskp + (size_t)(b * LL + l) * LL);
#pragma unroll
        for (int i = 0; i < 16; i++) mw[i] = mrow[lane + 32 * i];
    }
    uint32_t* mbrow = g_maskb + (size_t)(b * LL + l) * (LL / 32);
#pragma unroll
    for (int i = 0; i < 16; i++) {
        uint32_t nib = ((mw[i] & 0x01010101u) * 0x01020408u) >> 24;
        uint32_t v, cur = nib;
        v = __shfl_xor_sync(0xFFFFFFFFu, cur, 1);
        cur = (lane & 1) ? (v | (cur << 4)) : (cur | (v << 4));
        v = __shfl_xor_sync(0xFFFFFFFFu, cur, 2);
        cur = (lane & 2) ? (v | (cur << 8)) : (cur | (v << 8));
        v = __shfl_xor_sync(0xFFFFFFFFu, cur, 4);
        cur = (lane & 4) ? (v | (cur << 16)) : (cur | (v << 16));
        if ((lane & 7) == 0) mbrow[4 * i + (lane >> 3)] = cur;
    }
    float z = 0.f;
#pragma unroll
    for (int i = 0; i < 16; i++) {
        float4 ev = e4[lane + 32 * i];
        if (!(mw[i] & 0x000000FFu)) z += ev.x;
        if (!(mw[i] & 0x0000FF00u)) z += ev.y;
        if (!(mw[i] & 0x00FF0000u)) z += ev.z;
        if (!(mw[i] & 0xFF000000u)) z += ev.w;
    }
#pragma unroll
    for (int o = 16; o; o >>= 1) z += __shfl_xor_sync(0xFFFFFFFFu, z, o);
    float zi = 1.f / z;
    if (lane == 0) g_zinv[b * LL + l] = zi;
    float4* arow = (float4*)(attn + ((size_t)b * LL + l) * LL);
#pragma unroll
    for (int i = 0; i < 16; i++) {
        uint32_t m = mw[i];
        float4 ev = e4[lane + 32 * i];
        float4 o4;
        o4.x = (m & 0x000000FFu) ? 0.f : ev.x * zi;
        o4.y = (m & 0x0000FF00u) ? 0.f : ev.y * zi;
        o4.z = (m & 0x00FF0000u) ? 0.f : ev.z * zi;
        o4.w = (m & 0xFF000000u) ? 0.f : ev.w * zi;
        arow[lane + 32 * i] = o4;
    }
}

// ================= Pass 5 (preferred): 64x128 tile, 3-stage, 72KB dyn SMEM =================
// CTA tile 64(l) x 128(d), K-chunk 64(s). Stage st: [A 8KB | B 16KB] = 24KB.
// 8 warps: warpM = wid&1 (32 rows), warpN = wid>>1 (32 cols). Grid 2048 -> 6.92 waves.
#define STG_SZ 24576u
#define B_OFF  8192u

__global__ __launch_bounds__(256, 2) void gemm_kernel72(float* __restrict__ out) {
    extern __shared__ __align__(128) unsigned char dsm[];
    uint32_t sb = smem_u32(dsm);
    int tid = threadIdx.x, wid = tid >> 5, lane = tid & 31;
    int b = blockIdx.z, l0 = blockIdx.y * 64, d0 = blockIdx.x * 128;
    int warpM = wid & 1, warpN = wid >> 1;

    float acc[2][4][4];
#pragma unroll
    for (int i = 0; i < 2; i++)
#pragma unroll
        for (int j = 0; j < 4; j++)
#pragma unroll
            for (int q = 0; q < 4; q++) acc[i][j][q] = 0.f;

    int sub = lane >> 3, l7 = lane & 7;
    int rA0 = warpM * 32 + (sub & 1) * 8 + l7;   // + mi*16 (rows 0..63)
    int chA = (sub >> 1);                         // + ki*2
    int rB0 = warpN * 32 + (sub >> 1) * 8 + l7;  // + p*16 (rows 0..127)
    int chB = (sub & 1);                          // + ki*2

    // A staging: row = tid>>2 (0..63), q = tid&3 -> chunks 2q, 2q+1 (16 s-bits)
    int arow_s = tid >> 2, aq = tid & 3;
    const uint32_t* mpb = g_maskb + (size_t)(b * LL + l0 + arow_s) * (LL / 32);
    int ashift = (aq & 1) * 16;
    uint32_t aso0 = SA(arow_s, 2 * aq), aso1 = SA(arow_s, 2 * aq + 1);
    // B staging: srow = tid>>1 (0..127), 4 chunks
    int srow = tid >> 1;
    int sc4 = (tid & 1) * 4;
    const __half* up = g_ut + ((size_t)(b * DD + d0 + srow)) * LL + sc4 * 8;
    uint32_t so[4];
#pragma unroll
    for (int j = 0; j < 4; j++) so[j] = SA(srow, sc4 + j);

    // ---- prologue: stages 0 and 1 ----
#pragma unroll
    for (int st = 0; st < 2; st++) {
        uint32_t ab = sb + (uint32_t)st * STG_SZ;
        uint32_t mb = (mpb[2 * st + (aq >> 1)] >> ashift) & 0xFFFFu;
        uint32_t r[8];
        expand_bits16(mb, r);
        STS128V(ab + aso0, r[0], r[1], r[2], r[3]);
        STS128V(ab + aso1, r[4], r[5], r[6], r[7]);
#pragma unroll
        for (int j = 0; j < 4; j++)
            CPASYNC16(ab + B_OFF + so[j], (const void*)(up + st * 64 + j * 8));
        CPCOMMIT();
    }

    int st = 0;  // kt % 3
    for (int kt = 0; kt < 32; ++kt) {
        CPWAIT1();
        __syncthreads();

        int stn = st + 2; if (stn >= 3) stn -= 3;
        uint32_t nb = sb + (uint32_t)stn * STG_SZ;

        // ---- cp.async B(kt+2) ----
        if (kt < 30) {
            int s0n = (kt + 2) * 64;
#pragma unroll
            for (int j = 0; j < 4; j++)
                CPASYNC16(nb + B_OFF + so[j], (const void*)(up + s0n + j * 8));
        }
        CPCOMMIT();

        // ---- LDG bits A(kt+2) ----
        uint32_t mb = 0;
        if (kt < 30) mb = (mpb[2 * (kt + 2) + (aq >> 1)] >> ashift) & 0xFFFFu;

        // ---- compute chunk kt ----
        uint32_t abase = sb + (uint32_t)st * STG_SZ;
        uint32_t bbase = abase + B_OFF;
#pragma unroll
        for (int ki = 0; ki < 4; ki++) {
            uint32_t af[2][4];
#pragma unroll
            for (int mi = 0; mi < 2; mi++)
                ldsm4(af[mi], abase + SA(rA0 + mi * 16, ki * 2 + chA));
#pragma unroll
            for (int p = 0; p < 2; p++) {
                uint32_t bf[4];
                ldsm4(bf, bbase + SA(rB0 + p * 16, ki * 2 + chB));
#pragma unroll
                for (int mi = 0; mi < 2; mi++) {
                    mma_f16(acc[mi][2 * p], af[mi], bf);
                    mma_f16(acc[mi][2 * p + 1], af[mi], bf + 2);
                }
            }
        }

        // ---- expand + STS A(kt+2) ----
        if (kt < 30) {
            uint32_t r[8];
            expand_bits16(mb, r);
            STS128V(nb + aso0, r[0], r[1], r[2], r[3]);
            STS128V(nb + aso1, r[4], r[5], r[6], r[7]);
        }
        if (++st == 3) st = 0;
    }

    // epilogue
    int g = lane >> 2, tg = lane & 3;
#pragma unroll
    for (int mi = 0; mi < 2; mi++) {
#pragma unroll
        for (int h = 0; h < 2; h++) {
            int row = warpM * 32 + mi * 16 + h * 8 + g;
            float zi = g_zinv[b * LL + l0 + row];
            float* orow = out + ((size_t)(b * LL + l0 + row)) * DD + d0 + warpN * 32;
#pragma unroll
            for (int ni = 0; ni < 4; ni++) {
                float2 val;
                val.x = acc[mi][ni][h * 2] * zi;
                val.y = acc[mi][ni][h * 2 + 1] * zi;
                *(float2*)(orow + ni * 8 + tg * 2) = val;
            }
        }
    }
}

// ================= Pass 5 (fallback): 48KB static, 2-stage B, bitpacked A, 128x128 =================
__global__ __launch_bounds__(256, 2) void gemm_kernel48(float* __restrict__ out) {
    __shared__ __align__(128) unsigned char smem[49152];
    uint32_t sb = smem_u32(smem);
    int tid = threadIdx.x, wid = tid >> 5, lane = tid & 31;
    int b = blockIdx.z, l0 = blockIdx.y * 128, d0 = blockIdx.x * 128;
    int warpM = wid & 3, warpN = wid >> 2;

    float acc[2][8][4];
#pragma unroll
    for (int i = 0; i < 2; i++)
#pragma unroll
        for (int j = 0; j < 8; j++)
#pragma unroll
            for (int q = 0; q < 4; q++) acc[i][j][q] = 0.f;

    int sub = lane >> 3, l7 = lane & 7;
    int rA0 = warpM * 32 + (sub & 1) * 8 + l7;
    int chA = (sub >> 1);
    int rB0 = warpN * 64 + (sub >> 1) * 8 + l7;
    int chB = (sub & 1);

    int srow = tid >> 1;
    int sc4 = (tid & 1) * 4;
    const uint32_t* mpb = g_maskb + (size_t)(b * LL + l0 + srow) * (LL / 32) + (tid & 1);
    const __half* up = g_ut + ((size_t)(b * DD + d0 + srow)) * LL + sc4 * 8;
    uint32_t so[4];
#pragma unroll
    for (int j = 0; j < 4; j++) so[j] = SA(srow, sc4 + j);

#pragma unroll
    for (int j = 0; j < 4; j++)
        CPASYNC16(sb + 16384u + so[j], (const void*)(up + 0 + j * 8));
    CPCOMMIT();
#pragma unroll
    for (int j = 0; j < 4; j++)
        CPASYNC16(sb + 32768u + so[j], (const void*)(up + 64 + j * 8));
    CPCOMMIT();
    {
        uint32_t r[16];
        expand_bits(mpb[0], r);
        STS128V(sb + so[0], r[0], r[1], r[2], r[3]);
        STS128V(sb + so[1], r[4], r[5], r[6], r[7]);
        STS128V(sb + so[2], r[8], r[9], r[10], r[11]);
        STS128V(sb + so[3], r[12], r[13], r[14], r[15]);
    }
    uint32_t mbits = mpb[2];
    CPWAIT1();
    __syncthreads();

    for (int kt = 0; kt < 32; ++kt) {
        uint32_t bbase = sb + 16384u + (uint32_t)(kt & 1) * 16384u;
#pragma unroll
        for (int ki = 0; ki < 4; ki++) {
            uint32_t af[2][4];
#pragma unroll
            for (int mi = 0; mi < 2; mi++)
                ldsm4(af[mi], sb + SA(rA0 + mi * 16, ki * 2 + chA));
#pragma unroll
            for (int p = 0; p < 4; p++) {
                uint32_t bf[4];
                ldsm4(bf, bbase + SA(rB0 + p * 16, ki * 2 + chB));
#pragma unroll
                for (int mi = 0; mi < 2; mi++) {
                    mma_f16(acc[mi][2 * p], af[mi], bf);
                    mma_f16(acc[mi][2 * p + 1], af[mi], bf + 2);
                }
            }
        }
        if (kt == 31) break;
        __syncthreads();
        {
            uint32_t r[16];
            expand_bits(mbits, r);
            STS128V(sb + so[0], r[0], r[1], r[2], r[3]);
            STS128V(sb + so[1], r[4], r[5], r[6], r[7]);
            STS128V(sb + so[2], r[8], r[9], r[10], r[11]);
            STS128V(sb + so[3], r[12], r[13], r[14], r[15]);
        }
        if (kt < 30) {
            int s0n = (kt + 2) * 64;
            mbits = mpb[2 * (kt + 2)];
#pragma unroll
            for (int j = 0; j < 4; j++)
                CPASYNC16(sb + 16384u + (uint32_t)(kt & 1) * 16384u + so[j],
                          (const void*)(up + s0n + j * 8));
        }
        CPCOMMIT();
        CPWAIT1();
        __syncthreads();
    }

    int g = lane >> 2, tg = lane & 3;
#pragma unroll
    for (int mi = 0; mi < 2; mi++) {
#pragma unroll
        for (int h = 0; h < 2; h++) {
            int row = warpM * 32 + mi * 16 + h * 8 + g;
            float zi = g_zinv[b * LL + l0 + row];
            float* orow = out + ((size_t)(b * LL + l0 + row)) * DD + d0 + warpN * 64;
#pragma unroll
            for (int ni = 0; ni < 8; ni++) {
                float2 val;
                val.x = acc[mi][ni][h * 2] * zi;
                val.y = acc[mi][ni][h * 2 + 1] * zi;
                *(float2*)(orow + ni * 8 + tg * 2) = val;
            }
        }
    }
}

// ---------------- launch ----------------
extern "C" void kernel_launch(void* const* d_in, const int* in_sizes, int n_in,
                              void* d_out, int out_size) {
    (void)in_sizes; (void)n_in; (void)out_size;
    const float* k = (const float*)d_in[1];
    const float* v = (const float*)d_in[2];
    const void* mask = d_in[3];
    const float* W2 = (const float*)d_in[6];
    const float* b2 = (const float*)d_in[7];

    float* out = (float*)d_out;                // [B, L, D]
    float* attn = out + (size_t)BB * LL * DD;  // [B, L, L]

    detect_kernel<<<1, 1024>>>((const unsigned int*)mask);
    ks_kernel<<<BB * LL / 8, 256>>>(k, W2, b2);
    maxexp_kernel<<<BB, 256>>>();
    ut_kernel<<<dim3(DD / 64, LL / 64, BB), 256>>>(v);
    zattn_kernel<<<BB * LL / 8, 256>>>(mask, attn);

    cudaError_t e = cudaFuncSetAttribute(gemm_kernel72,
                                         cudaFuncAttributeMaxDynamicSharedMemorySize, 73728);
    if (e == cudaSuccess) {
        gemm_kernel72<<<dim3(DD / 128, LL / 64, BB), 256, 73728>>>(out);
    } else {
        (void)cudaGetLastError();
        gemm_kernel48<<<dim3(DD / 128, LL / 128, BB), 256>>>(out);
    }
}

// round 13
// speedup vs baseline: 1.1904x; 1.1904x over previous
#include <cuda_runtime.h>
#include <cuda_bf16.h>
#include <cuda_fp16.h>
#include <cstdint>
#include <cstddef>

#define BB 8
#define LL 2048
#define DD 1024

// ---------------- scratch (device globals; allocation-free) ----------------
__device__ float g_ks[BB * LL];
__device__ float g_e[BB * LL];
__device__ float g_zinv[BB * LL];
__device__ int g_is32;
__device__ uint32_t g_maskb[(size_t)BB * LL * (LL / 32)];  // bit s%32 of word: 1 = masked
__device__ __half g_ut[(size_t)BB * DD * LL];              // U^T fp16: [b][d][s]

// ---------------- helpers ----------------
static __device__ __forceinline__ uint32_t smem_u32(const void* p) {
    uint32_t a;
    asm("{ .reg .u64 t; cvta.to.shared.u64 t, %1; cvt.u32.u64 %0, t; }" : "=r"(a) : "l"(p));
    return a;
}

#define STS128V(a, r0, r1, r2, r3) \
    asm volatile("st.shared.v4.b32 [%0], {%1, %2, %3, %4};" :: "r"(a), "r"(r0), "r"(r1), "r"(r2), "r"(r3) : "memory")

#define CPASYNC16(dst, src) \
    asm volatile("cp.async.cg.shared.global [%0], [%1], 16;" :: "r"(dst), "l"(src) : "memory")
#define CPCOMMIT() asm volatile("cp.async.commit_group;" ::: "memory")
#define CPWAIT1() asm volatile("cp.async.wait_group 1;" ::: "memory")

static __device__ __forceinline__ void ldsm4(uint32_t* r, uint32_t addr) {
    asm volatile("ldmatrix.sync.aligned.m8n8.x4.shared.b16 {%0,%1,%2,%3}, [%4];"
                 : "=r"(r[0]), "=r"(r[1]), "=r"(r[2]), "=r"(r[3]) : "r"(addr));
}

static __device__ __forceinline__ void mma_f16(float* c, const uint32_t* a, const uint32_t* b) {
    asm volatile(
        "mma.sync.aligned.m16n8k16.row.col.f32.f16.f16.f32 "
        "{%0,%1,%2,%3}, {%4,%5,%6,%7}, {%8,%9}, {%0,%1,%2,%3};"
        : "+f"(c[0]), "+f"(c[1]), "+f"(c[2]), "+f"(c[3])
        : "r"(a[0]), "r"(a[1]), "r"(a[2]), "r"(a[3]), "r"(b[0]), "r"(b[1]));
}

// swizzled SMEM offset: tiles are 128 rows x 64 fp16 (128B rows, 8 x 16B chunks)
#define SA(row, chunk) ((uint32_t)((row) * 128 + ((((uint32_t)(chunk)) ^ ((uint32_t)(row) & 7u)) << 4)))

// expand 32 mask bits -> 16 fp16x2 words (1.0 where bit==0)
static __device__ __forceinline__ void expand_bits(uint32_t m, uint32_t* r) {
#pragma unroll
    for (int i = 0; i < 16; i++) {
        uint32_t lo = (m >> (2 * i)) & 1u;
        uint32_t hi = (m >> (2 * i + 1)) & 1u;
        r[i] = (lo ? 0u : 0x3C00u) | (hi ? 0u : 0x3C000000u);
    }
}

// ---------------- Pass 0: detect mask dtype (int32 vs uint8) ----------------
__global__ void detect_kernel(const unsigned int* m) {
    __shared__ int s;
    if (threadIdx.x == 0) s = 0;
    __syncthreads();
    if (m[threadIdx.x] & 0xFFFFFF00u) atomicOr(&s, 1);
    __syncthreads();
    if (threadIdx.x == 0) g_is32 = s ? 0 : 1;
}

// ---------------- Pass 1: k_s[b,s] = k . W2 + b2 ----------------
__global__ __launch_bounds__(256) void ks_kernel(const float* __restrict__ k,
                                                 const float* __restrict__ W2,
                                                 const float* __restrict__ b2) {
    int w = threadIdx.x >> 5, lane = threadIdx.x & 31;
    int r = blockIdx.x * 8 + w;
    const float4* kr = (const float4*)(k + (size_t)r * DD);
    const float4* w4 = (const float4*)W2;
    float s = 0.f;
#pragma unroll
    for (int i = 0; i < 8; i++) {
        float4 a = kr[lane + 32 * i];
        float4 b = w4[lane + 32 * i];
        s += a.x * b.x + a.y * b.y + a.z * b.z + a.w * b.w;
    }
#pragma unroll
    for (int o = 16; o; o >>= 1) s += __shfl_xor_sync(0xFFFFFFFFu, s, o);
    if (lane == 0) g_ks[r] = s + b2[0];
}

// ---------------- Pass 2: per-b max and e = exp(ks - max) ----------------
__global__ __launch_bounds__(256) void maxexp_kernel() {
    int b = blockIdx.x;
    __shared__ float red[256];
    float m = -1e30f;
    for (int i = threadIdx.x; i < LL; i += 256) m = fmaxf(m, g_ks[b * LL + i]);
    red[threadIdx.x] = m;
    __syncthreads();
    for (int s = 128; s; s >>= 1) {
        if (threadIdx.x < s) red[threadIdx.x] = fmaxf(red[threadIdx.x], red[threadIdx.x + s]);
        __syncthreads();
    }
    float M = red[0];
    for (int i = threadIdx.x; i < LL; i += 256) g_e[b * LL + i] = expf(g_ks[b * LL + i] - M);
}

// ---------------- Pass 3: U^T fp16 build, 64x64 tiles, vectorized ----------------
__global__ __launch_bounds__(256) void ut_kernel(const float* __restrict__ v) {
    __shared__ float tile[64][65];
    int b = blockIdx.z;
    int s0 = blockIdx.y * 64, d0 = blockIdx.x * 64;
    int t = threadIdx.x;
    int sl = t >> 2, f4 = t & 3;
    float e = g_e[b * LL + s0 + sl];
    const float4* vr = (const float4*)(v + ((size_t)b * LL + s0 + sl) * DD + d0);
#pragma unroll
    for (int i = 0; i < 4; i++) {
        int c4 = f4 + 4 * i;
        float4 val = vr[c4];
        tile[sl][c4 * 4 + 0] = val.x * e;
        tile[sl][c4 * 4 + 1] = val.y * e;
        tile[sl][c4 * 4 + 2] = val.z * e;
        tile[sl][c4 * 4 + 3] = val.w * e;
    }
    __syncthreads();
    int dl = t >> 2, q = t & 3;
    __half* orow = g_ut + ((size_t)b * DD + d0 + dl) * LL + s0 + q * 16;
    uint32_t pk[8];
#pragma unroll
    for (int j = 0; j < 8; j++) {
        __half2 h2 = __floats2half2_rn(tile[q * 16 + 2 * j][dl], tile[q * 16 + 2 * j + 1][dl]);
        pk[j] = *(uint32_t*)&h2;
    }
    ((uint4*)orow)[0] = make_uint4(pk[0], pk[1], pk[2], pk[3]);
    ((uint4*)orow)[1] = make_uint4(pk[4], pk[5], pk[6], pk[7]);
}

// ---------------- Pass 4: fused bitpack + Z + attn (512 threads, 16 rows/block) ----------------
__global__ __launch_bounds__(512) void zattn_kernel(const void* __restrict__ maskp,
                                                    float* __restrict__ attn) {
    __shared__ __align__(16) float se[LL];
    int b = blockIdx.x >> 7;               // L/16 = 128 blocks per batch
    int l0 = (blockIdx.x & 127) * 16;
    for (int i = threadIdx.x; i < LL; i += 512) se[i] = g_e[b * LL + i];
    __syncthreads();
    int w = threadIdx.x >> 5, lane = threadIdx.x & 31;
    int l = l0 + w;
    const float4* e4 = (const float4*)se;
    uint32_t mw[16];
    if (g_is32) {
        const uint4* mrow = (const uint4*)((const int*)maskp + (size_t)(b * LL + l) * LL);
#pragma unroll
        for (int i = 0; i < 16; i++) {
            uint4 wv = mrow[lane + 32 * i];
            mw[i] = (wv.x ? 1u : 0u) | (wv.y ? 0x100u : 0u) |
                    (wv.z ? 0x10000u : 0u) | (wv.w ? 0x1000000u : 0u);
        }
    } else {
        const uint32_t* mrow = (const uint32_t*)((const unsigned char*)maskp + (size_t)(b * LL + l) * LL);
#pragma unroll
        for (int i = 0; i < 16; i++) mw[i] = mrow[lane + 32 * i];
    }
    uint32_t* mbrow = g_maskb + (size_t)(b * LL + l) * (LL / 32);
#pragma unroll
    for (int i = 0; i < 16; i++) {
        uint32_t nib = ((mw[i] & 0x01010101u) * 0x01020408u) >> 24;
        uint32_t v, cur = nib;
        v = __shfl_xor_sync(0xFFFFFFFFu, cur, 1);
        cur = (lane & 1) ? (v | (cur << 4)) : (cur | (v << 4));
        v = __shfl_xor_sync(0xFFFFFFFFu, cur, 2);
        cur = (lane & 2) ? (v | (cur << 8)) : (cur | (v << 8));
        v = __shfl_xor_sync(0xFFFFFFFFu, cur, 4);
        cur = (lane & 4) ? (v | (cur << 16)) : (cur | (v << 16));
        if ((lane & 7) == 0) mbrow[4 * i + (lane >> 3)] = cur;
    }
    float z = 0.f;
#pragma unroll
    for (int i = 0; i < 16; i++) {
        float4 ev = e4[lane + 32 * i];
        if (!(mw[i] & 0x000000FFu)) z += ev.x;
        if (!(mw[i] & 0x0000FF00u)) z += ev.y;
        if (!(mw[i] & 0x00FF0000u)) z += ev.z;
        if (!(mw[i] & 0xFF000000u)) z += ev.w;
    }
#pragma unroll
    for (int o = 16; o; o >>= 1) z += __shfl_xor_sync(0xFFFFFFFFu, z, o);
    float zi = 1.f / z;
    if (lane == 0) g_zinv[b * LL + l] = zi;
    float4* arow = (float4*)(attn + ((size_t)b * LL + l) * LL);
#pragma unroll
    for (int i = 0; i < 16; i++) {
        uint32_t m = mw[i];
        float4 ev = e4[lane + 32 * i];
        float4 o4;
        o4.x = (m & 0x000000FFu) ? 0.f : ev.x * zi;
        o4.y = (m & 0x0000FF00u) ? 0.f : ev.y * zi;
        o4.z = (m & 0x00FF0000u) ? 0.f : ev.z * zi;
        o4.w = (m & 0xFF000000u) ? 0.f : ev.w * zi;
        arow[lane + 32 * i] = o4;
    }
}

// ================= Pass 5 (preferred): 3-stage pipelined fp16 GEMM, 96KB dyn SMEM =================
// A operand from bit-packed mask: 1 LDG.32 + register expansion per thread per chunk.
__global__ __launch_bounds__(256, 2) void gemm_kernel96(float* __restrict__ out) {
    extern __shared__ __align__(128) unsigned char dsm[];
    uint32_t sb = smem_u32(dsm);
    int tid = threadIdx.x, wid = tid >> 5, lane = tid & 31;
    int b = blockIdx.z, l0 = blockIdx.y * 128, d0 = blockIdx.x * 128;
    int warpM = wid & 3, warpN = wid >> 2;

    float acc[2][8][4];
#pragma unroll
    for (int i = 0; i < 2; i++)
#pragma unroll
        for (int j = 0; j < 8; j++)
#pragma unroll
            for (int q = 0; q < 4; q++) acc[i][j][q] = 0.f;

    int sub = lane >> 3, l7 = lane & 7;
    int rA0 = warpM * 32 + (sub & 1) * 8 + l7;
    int chA = (sub >> 1);
    int rB0 = warpN * 64 + (sub >> 1) * 8 + l7;
    int chB = (sub & 1);

    int srow = tid >> 1;
    int sc4 = (tid & 1) * 4;
    const uint32_t* mpb = g_maskb + (size_t)(b * LL + l0 + srow) * (LL / 32) + (tid & 1);
    const __half* up = g_ut + ((size_t)(b * DD + d0 + srow)) * LL + sc4 * 8;
    uint32_t so[4];
#pragma unroll
    for (int j = 0; j < 4; j++) so[j] = SA(srow, sc4 + j);

    // ---- prologue: stages 0 and 1 ----
#pragma unroll
    for (int st = 0; st < 2; st++) {
        uint32_t ab = sb + (uint32_t)st * 32768u;
        uint32_t r[16];
        expand_bits(mpb[2 * st], r);
        STS128V(ab + so[0], r[0], r[1], r[2], r[3]);
        STS128V(ab + so[1], r[4], r[5], r[6], r[7]);
        STS128V(ab + so[2], r[8], r[9], r[10], r[11]);
        STS128V(ab + so[3], r[12], r[13], r[14], r[15]);
#pragma unroll
        for (int j = 0; j < 4; j++)
            CPASYNC16(ab + 16384u + so[j], (const void*)(up + st * 64 + j * 8));
        CPCOMMIT();
    }

    int st = 0;  // kt % 3
    for (int kt = 0; kt < 32; ++kt) {
        CPWAIT1();       // B(kt) arrived (only B(kt+1) pending)
        __syncthreads(); // compute(kt-1) done everywhere; stage (kt+2)%3 free; stage kt visible

        int stn = st + 2; if (stn >= 3) stn -= 3;
        uint32_t nb = sb + (uint32_t)stn * 32768u;

        // ---- cp.async B(kt+2) (pure DMA, overlaps compute) ----
        if (kt < 30) {
            int s0n = (kt + 2) * 64;
#pragma unroll
            for (int j = 0; j < 4; j++)
                CPASYNC16(nb + 16384u + so[j], (const void*)(up + s0n + j * 8));
        }
        CPCOMMIT();

        // ---- LDG bit-word A(kt+2) (tiny; latency covered by compute) ----
        uint32_t mbits = 0;
        if (kt < 30) mbits = mpb[2 * (kt + 2)];

        // ---- compute chunk kt from stage st ----
        uint32_t abase = sb + (uint32_t)st * 32768u;
        uint32_t bbase = abase + 16384u;
#pragma unroll
        for (int ki = 0; ki < 4; ki++) {
            uint32_t af[2][4];
#pragma unroll
            for (int mi = 0; mi < 2; mi++)
                ldsm4(af[mi], abase + SA(rA0 + mi * 16, ki * 2 + chA));
#pragma unroll
            for (int p = 0; p < 4; p++) {
                uint32_t bf[4];
                ldsm4(bf, bbase + SA(rB0 + p * 16, ki * 2 + chB));
#pragma unroll
                for (int mi = 0; mi < 2; mi++) {
                    mma_f16(acc[mi][2 * p], af[mi], bf);
                    mma_f16(acc[mi][2 * p + 1], af[mi], bf + 2);
                }
            }
        }

        // ---- expand + STS A(kt+2) ----
        if (kt < 30) {
            uint32_t r[16];
            expand_bits(mbits, r);
            STS128V(nb + so[0], r[0], r[1], r[2], r[3]);
            STS128V(nb + so[1], r[4], r[5], r[6], r[7]);
            STS128V(nb + so[2], r[8], r[9], r[10], r[11]);
            STS128V(nb + so[3], r[12], r[13], r[14], r[15]);
        }
        if (++st == 3) st = 0;
    }

    // epilogue
    int g = lane >> 2, tg = lane & 3;
#pragma unroll
    for (int mi = 0; mi < 2; mi++) {
#pragma unroll
        for (int h = 0; h < 2; h++) {
            int row = warpM * 32 + mi * 16 + h * 8 + g;
            float zi = g_zinv[b * LL + l0 + row];
            float* orow = out + ((size_t)(b * LL + l0 + row)) * DD + d0 + warpN * 64;
#pragma unroll
            for (int ni = 0; ni < 8; ni++) {
                float2 val;
                val.x = acc[mi][ni][h * 2] * zi;
                val.y = acc[mi][ni][h * 2 + 1] * zi;
                *(float2*)(orow + ni * 8 + tg * 2) = val;
            }
        }
    }
}

// ================= Pass 5 (fallback): 48KB static, 2-stage B, bitpacked A =================
__global__ __launch_bounds__(256, 2) void gemm_kernel48(float* __restrict__ out) {
    __shared__ __align__(128) unsigned char smem[49152];
    uint32_t sb = smem_u32(smem);
    int tid = threadIdx.x, wid = tid >> 5, lane = tid & 31;
    int b = blockIdx.z, l0 = blockIdx.y * 128, d0 = blockIdx.x * 128;
    int warpM = wid & 3, warpN = wid >> 2;

    float acc[2][8][4];
#pragma unroll
    for (int i = 0; i < 2; i++)
#pragma unroll
        for (int j = 0; j < 8; j++)
#pragma unroll
            for (int q = 0; q < 4; q++) acc[i][j][q] = 0.f;

    int sub = lane >> 3, l7 = lane & 7;
    int rA0 = warpM * 32 + (sub & 1) * 8 + l7;
    int chA = (sub >> 1);
    int rB0 = warpN * 64 + (sub >> 1) * 8 + l7;
    int chB = (sub & 1);

    int srow = tid >> 1;
    int sc4 = (tid & 1) * 4;
    const uint32_t* mpb = g_maskb + (size_t)(b * LL + l0 + srow) * (LL / 32) + (tid & 1);
    const __half* up = g_ut + ((size_t)(b * DD + d0 + srow)) * LL + sc4 * 8;
    uint32_t so[4];
#pragma unroll
    for (int j = 0; j < 4; j++) so[j] = SA(srow, sc4 + j);

#pragma unroll
    for (int j = 0; j < 4; j++)
        CPASYNC16(sb + 16384u + so[j], (const void*)(up + 0 + j * 8));
    CPCOMMIT();
#pragma unroll
    for (int j = 0; j < 4; j++)
        CPASYNC16(sb + 32768u + so[j], (const void*)(up + 64 + j * 8));
    CPCOMMIT();
    {
        uint32_t r[16];
        expand_bits(mpb[0], r);
        STS128V(sb + so[0], r[0], r[1], r[2], r[3]);
        STS128V(sb + so[1], r[4], r[5], r[6], r[7]);
        STS128V(sb + so[2], r[8], r[9], r[10], r[11]);
        STS128V(sb + so[3], r[12], r[13], r[14], r[15]);
    }
    uint32_t mbits = mpb[2];
    CPWAIT1();
    __syncthreads();

    for (int kt = 0; kt < 32; ++kt) {
        uint32_t bbase = sb + 16384u + (uint32_t)(kt & 1) * 16384u;
#pragma unroll
        for (int ki = 0; ki < 4; ki++) {
            uint32_t af[2][4];
#pragma unroll
            for (int mi = 0; mi < 2; mi++)
                ldsm4(af[mi], sb + SA(rA0 + mi * 16, ki * 2 + chA));
#pragma unroll
            for (int p = 0; p < 4; p++) {
                uint32_t bf[4];
                ldsm4(bf, bbase + SA(rB0 + p * 16, ki * 2 + chB));
#pragma unroll
                for (int mi = 0; mi < 2; mi++) {
                    mma_f16(acc[mi][2 * p], af[mi], bf);
                    mma_f16(acc[mi][2 * p + 1], af[mi], bf + 2);
                }
            }
        }
        if (kt == 31) break;
        __syncthreads();
        {
            uint32_t r[16];
            expand_bits(mbits, r);
            STS128V(sb + so[0], r[0], r[1], r[2], r[3]);
            STS128V(sb + so[1], r[4], r[5], r[6], r[7]);
            STS128V(sb + so[2], r[8], r[9], r[10], r[11]);
            STS128V(sb + so[3], r[12], r[13], r[14], r[15]);
        }
        if (kt < 30) {
            int s0n = (kt + 2) * 64;
            mbits = mpb[2 * (kt + 2)];
#pragma unroll
            for (int j = 0; j < 4; j++)
                CPASYNC16(sb + 16384u + (uint32_t)(kt & 1) * 16384u + so[j],
                          (const void*)(up + s0n + j * 8));
        }
        CPCOMMIT();
        CPWAIT1();
        __syncthreads();
    }

    int g = lane >> 2, tg = lane & 3;
#pragma unroll
    for (int mi = 0; mi < 2; mi++) {
#pragma unroll
        for (int h = 0; h < 2; h++) {
            int row = warpM * 32 + mi * 16 + h * 8 + g;
            float zi = g_zinv[b * LL + l0 + row];
            float* orow = out + ((size_t)(b * LL + l0 + row)) * DD + d0 + warpN * 64;
#pragma unroll
            for (int ni = 0; ni < 8; ni++) {
                float2 val;
                val.x = acc[mi][ni][h * 2] * zi;
                val.y = acc[mi][ni][h * 2 + 1] * zi;
                *(float2*)(orow + ni * 8 + tg * 2) = val;
            }
        }
    }
}

// ---------------- launch ----------------
extern "C" void kernel_launch(void* const* d_in, const int* in_sizes, int n_in,
                              void* d_out, int out_size) {
    (void)in_sizes; (void)n_in; (void)out_size;
    const float* k = (const float*)d_in[1];
    const float* v = (const float*)d_in[2];
    const void* mask = d_in[3];
    const float* W2 = (const float*)d_in[6];
    const float* b2 = (const float*)d_in[7];

    float* out = (float*)d_out;                // [B, L, D]
    float* attn = out + (size_t)BB * LL * DD;  // [B, L, L]

    detect_kernel<<<1, 1024>>>((const unsigned int*)mask);
    ks_kernel<<<BB * LL / 8, 256>>>(k, W2, b2);
    maxexp_kernel<<<BB, 256>>>();
    ut_kernel<<<dim3(DD / 64, LL / 64, BB), 256>>>(v);
    zattn_kernel<<<BB * LL / 16, 512>>>(mask, attn);

    dim3 grid(DD / 128, LL / 128, BB);
    cudaError_t e = cudaFuncSetAttribute(gemm_kernel96,
                                         cudaFuncAttributeMaxDynamicSharedMemorySize, 98304);
    if (e == cudaSuccess) {
        gemm_kernel96<<<grid, 256, 98304>>>(out);
    } else {
        (void)cudaGetLastError();
        gemm_kernel48<<<grid, 256>>>(out);
    }
}